// round 2
// baseline (speedup 1.0000x reference)
#include <cuda_runtime.h>
#include <math.h>

// ---------------- problem constants ----------------
#define BB      16
#define NN      128
#define RR      16256
#define OBJD    64
#define RELD    32
#define EFFD    100
#define RHID    150
#define RIN     160      // 2*OBJD + RELD
#define OIN     164      // OBJD + EFFD
#define OHID    100

#define TILE_R  128
#define NTILES  127      // RR / TILE_R
#define KSPLIT  18

#define XS      164      // activation smem row stride (floats) -> (164%32)!=0, conflict-free row pairs
#define WS      160      // weight-stage row stride
#define SRS     132      // scatter R-tile row stride

// scratch (device globals: allocation-free per harness rules)
__device__ float g_effects[BB * RR * EFFD];                 // ~104 MB
__device__ float g_part[KSPLIT * BB * NN * EFFD];           // ~14.7 MB
__device__ float g_er[BB * NN * EFFD];                      // ~0.8 MB

// ---------------- fused relation-MLP layer ----------------
// A: smem [128, XS];  W: global [K, NOUT] row-major;  out: smem (stride XS) or global (stride NOUT)
template<int K, int NOUT, int NJ, bool TO_GLOBAL>
__device__ __forceinline__ void mlp_layer(
    const float* A, const float* __restrict__ W, const float* __restrict__ bias,
    float* Cs, float* Cg, float* sW, int tid, int tx, int ty)
{
    float acc[8][NJ];
#pragma unroll
    for (int i = 0; i < 8; i++)
#pragma unroll
        for (int j = 0; j < NJ; j++) acc[i][j] = 0.f;

    constexpr int KPAD = (K + 15) & ~15;
    for (int k0 = 0; k0 < KPAD; k0 += 16) {
        __syncthreads();
        for (int idx = tid; idx < 16 * WS; idx += 256) {
            int kk = idx / WS;
            int c  = idx - kk * WS;
            int k  = k0 + kk;
            sW[idx] = (k < K && c < NOUT) ? W[k * NOUT + c] : 0.f;
        }
        __syncthreads();
#pragma unroll
        for (int kk = 0; kk < 16; ++kk) {
            float a[8], w[NJ];
#pragma unroll
            for (int i = 0; i < 8; i++) a[i] = A[(ty + 16 * i) * XS + k0 + kk];
#pragma unroll
            for (int j = 0; j < NJ; j++) w[j] = sW[kk * WS + tx + 16 * j];
#pragma unroll
            for (int i = 0; i < 8; i++)
#pragma unroll
                for (int j = 0; j < NJ; j++) acc[i][j] = fmaf(a[i], w[j], acc[i][j]);
        }
    }
    if (TO_GLOBAL) {
#pragma unroll
        for (int i = 0; i < 8; i++) {
            int r = ty + 16 * i;
#pragma unroll
            for (int j = 0; j < NJ; j++) {
                int c = tx + 16 * j;
                if (c < NOUT) Cg[r * NOUT + c] = fmaxf(acc[i][j] + bias[c], 0.f);
            }
        }
    } else {
#pragma unroll
        for (int i = 0; i < 8; i++) {
            int r = ty + 16 * i;
#pragma unroll
            for (int j = 0; j < NJ; j++) {
                int c = tx + 16 * j;
                float v = 0.f;
                if (c < NOUT) v = fmaxf(acc[i][j] + bias[c], 0.f);
                Cs[r * XS + c] = v;   // pad cols [NOUT,160) zeroed for next layer's KPAD loop
            }
        }
    }
}

// ---------------- kernel A: gather + 4-layer relation MLP ----------------
// grid (NTILES, BB), 256 threads
__global__ __launch_bounds__(256, 1)
void gather_mlp_kernel(const float* __restrict__ objects,
                       const float* __restrict__ srel,
                       const float* __restrict__ rrel,
                       const float* __restrict__ relinfo,
                       const float* __restrict__ rw1, const float* __restrict__ rb1,
                       const float* __restrict__ rw2, const float* __restrict__ rb2,
                       const float* __restrict__ rw3, const float* __restrict__ rb3,
                       const float* __restrict__ rw4, const float* __restrict__ rb4)
{
    extern __shared__ float smem[];
    float* bufX = smem;                    // 128 x XS
    float* bufH = bufX + NN * XS;          // 128 x XS (also S/R staging at stride SRS)
    float* sAux = bufH + NN * XS;          // 8192 floats: O[128x64], later W stage [16x160]

    const int tid = threadIdx.x;
    const int tx = tid & 15, ty = tid >> 4;
    const int t = blockIdx.x, b = blockIdx.y;
    const int r0 = t * TILE_R;

    // objects[b] -> sAux  [n*64 + d]
    const float* Ob = objects + (size_t)b * NN * OBJD;
    for (int i = tid; i < NN * OBJD; i += 256) sAux[i] = Ob[i];

    // relation_info -> bufX[:, 128:160]
    const float* RI = relinfo + ((size_t)b * RR + r0) * RELD;
    for (int i = tid; i < TILE_R * RELD; i += 256) {
        int r = i >> 5, c = i & 31;
        bufX[r * XS + 128 + c] = RI[i];
    }

    // gather: senders (pass 0) -> bufX[:,0:64], receivers (pass 1) -> bufX[:,64:128]
    for (int pass = 0; pass < 2; ++pass) {
        const float* Rel = pass ? rrel : srel;
        __syncthreads();
        for (int i = tid; i < NN * TILE_R; i += 256) {
            int n = i >> 7, r = i & 127;
            bufH[n * SRS + r] = Rel[((size_t)b * NN + n) * RR + r0 + r];
        }
        __syncthreads();
        float acc[8][4];
#pragma unroll
        for (int i = 0; i < 8; i++)
#pragma unroll
            for (int j = 0; j < 4; j++) acc[i][j] = 0.f;
        for (int n = 0; n < NN; ++n) {
            float a[8], w[4];
#pragma unroll
            for (int i = 0; i < 8; i++) a[i] = bufH[n * SRS + ty + 16 * i];
#pragma unroll
            for (int j = 0; j < 4; j++) w[j] = sAux[n * OBJD + tx + 16 * j];
#pragma unroll
            for (int i = 0; i < 8; i++)
#pragma unroll
                for (int j = 0; j < 4; j++) acc[i][j] = fmaf(a[i], w[j], acc[i][j]);
        }
#pragma unroll
        for (int i = 0; i < 8; i++)
#pragma unroll
            for (int j = 0; j < 4; j++)
                bufX[(ty + 16 * i) * XS + pass * 64 + tx + 16 * j] = acc[i][j];
    }

    float* sW = sAux;   // overwrites O after first layer's internal barrier
    float* effp = g_effects + ((size_t)b * RR + r0) * EFFD;

    mlp_layer<RIN,  RHID, 10, false>(bufX, rw1, rb1, bufH, nullptr, sW, tid, tx, ty);
    mlp_layer<RHID, RHID, 10, false>(bufH, rw2, rb2, bufX, nullptr, sW, tid, tx, ty);
    mlp_layer<RHID, RHID, 10, false>(bufX, rw3, rb3, bufH, nullptr, sW, tid, tx, ty);
    mlp_layer<RHID, EFFD, 7,  true >(bufH, rw4, rb4, nullptr, effp, sW, tid, tx, ty);
}

// ---------------- kernel B: scatter (split-K, deterministic partials) ----------------
// grid (KSPLIT, BB), 256 threads
__global__ __launch_bounds__(256, 1)
void scatter_kernel(const float* __restrict__ rrel)
{
    extern __shared__ float smem[];
    float* sR = smem;            // 128 x SRS
    float* sE = sR + NN * SRS;   // 128 x EFFD
    const int tid = threadIdx.x, tx = tid & 15, ty = tid >> 4;
    const int split = blockIdx.x, b = blockIdx.y;

    float acc[8][7];
#pragma unroll
    for (int i = 0; i < 8; i++)
#pragma unroll
        for (int j = 0; j < 7; j++) acc[i][j] = 0.f;

    for (int t = split; t < NTILES; t += KSPLIT) {
        int r0 = t * TILE_R;
        __syncthreads();
        for (int i = tid; i < NN * TILE_R; i += 256) {
            int n = i >> 7, r = i & 127;
            sR[n * SRS + r] = rrel[((size_t)b * NN + n) * RR + r0 + r];
        }
        const float* E = g_effects + ((size_t)b * RR + r0) * EFFD;
        for (int i = tid; i < TILE_R * EFFD; i += 256) sE[i] = E[i];
        __syncthreads();
        for (int r = 0; r < TILE_R; ++r) {
            float a[8], w[7];
#pragma unroll
            for (int i = 0; i < 8; i++) a[i] = sR[(ty + 16 * i) * SRS + r];
#pragma unroll
            for (int j = 0; j < 7; j++) {
                int c = tx + 16 * j;
                w[j] = (c < EFFD) ? sE[r * EFFD + c] : 0.f;
            }
#pragma unroll
            for (int i = 0; i < 8; i++)
#pragma unroll
                for (int j = 0; j < 7; j++) acc[i][j] = fmaf(a[i], w[j], acc[i][j]);
        }
    }

    float* P = g_part + ((size_t)split * BB + b) * NN * EFFD;
#pragma unroll
    for (int i = 0; i < 8; i++) {
        int n = ty + 16 * i;
#pragma unroll
        for (int j = 0; j < 7; j++) {
            int c = tx + 16 * j;
            if (c < EFFD) P[n * EFFD + c] = acc[i][j];
        }
    }
}

// ---------------- kernel C: reduce split-K partials ----------------
__global__ void reduce_kernel()
{
    int i = blockIdx.x * blockDim.x + threadIdx.x;
    if (i < BB * NN * EFFD) {
        float s = 0.f;
#pragma unroll
        for (int k = 0; k < KSPLIT; ++k)
            s += g_part[(size_t)k * (BB * NN * EFFD) + i];
        g_er[i] = s;
    }
}

// ---------------- kernel D: final object MLP + sigmoid ----------------
// grid (BB*NN), 128 threads, one row per block
__global__ __launch_bounds__(128)
void final_kernel(const float* __restrict__ objects,
                  const float* __restrict__ ow1, const float* __restrict__ ob1,
                  const float* __restrict__ ow2, const float* __restrict__ ob2,
                  float* __restrict__ out)
{
    __shared__ float y[OIN];
    __shared__ float red[128];
    const int row = blockIdx.x;
    const int t = threadIdx.x;

    if (t < OBJD) y[t] = objects[(size_t)row * OBJD + t];
    if (t < EFFD) y[OBJD + t] = g_er[(size_t)row * EFFD + t];
    __syncthreads();

    float v = 0.f;
    if (t < OHID) {
        float acc = ob1[t];
#pragma unroll 4
        for (int k = 0; k < OIN; ++k) acc = fmaf(y[k], ow1[k * OHID + t], acc);
        v = fmaxf(acc, 0.f) * ow2[t];
    }
    red[t] = v;
    __syncthreads();
    for (int s = 64; s > 0; s >>= 1) {
        if (t < s) red[t] += red[t + s];
        __syncthreads();
    }
    if (t == 0) out[row] = 1.f / (1.f + expf(-(red[0] + ob2[0])));
}

// ---------------- launch ----------------
extern "C" void kernel_launch(void* const* d_in, const int* in_sizes, int n_in,
                              void* d_out, int out_size)
{
    const float* objects = (const float*)d_in[0];
    const float* srel    = (const float*)d_in[1];
    const float* rrel    = (const float*)d_in[2];
    const float* relinfo = (const float*)d_in[3];
    const float* rw1 = (const float*)d_in[4];
    const float* rb1 = (const float*)d_in[5];
    const float* rw2 = (const float*)d_in[6];
    const float* rb2 = (const float*)d_in[7];
    const float* rw3 = (const float*)d_in[8];
    const float* rb3 = (const float*)d_in[9];
    const float* rw4 = (const float*)d_in[10];
    const float* rb4 = (const float*)d_in[11];
    const float* ow1 = (const float*)d_in[12];
    const float* ob1 = (const float*)d_in[13];
    const float* ow2 = (const float*)d_in[14];
    const float* ob2 = (const float*)d_in[15];
    float* out = (float*)d_out;

    const int GATHER_SMEM  = (2 * NN * XS + 8192) * (int)sizeof(float);   // 200704 B
    const int SCATTER_SMEM = (NN * SRS + NN * EFFD) * (int)sizeof(float); // 118784 B

    cudaFuncSetAttribute(gather_mlp_kernel, cudaFuncAttributeMaxDynamicSharedMemorySize, GATHER_SMEM);
    cudaFuncSetAttribute(scatter_kernel,   cudaFuncAttributeMaxDynamicSharedMemorySize, SCATTER_SMEM);

    gather_mlp_kernel<<<dim3(NTILES, BB), 256, GATHER_SMEM>>>(
        objects, srel, rrel, relinfo,
        rw1, rb1, rw2, rb2, rw3, rb3, rw4, rb4);

    scatter_kernel<<<dim3(KSPLIT, BB), 256, SCATTER_SMEM>>>(rrel);

    reduce_kernel<<<(BB * NN * EFFD + 255) / 256, 256>>>();

    final_kernel<<<BB * NN, 128>>>(objects, ow1, ob1, ow2, ob2, out);
}